// round 1
// baseline (speedup 1.0000x reference)
#include <cuda_runtime.h>
#include <math.h>

// Problem constants
#define NBATCH 8
#define NPTS   2048
#define NFEAT  32
#define NROWS  (NBATCH * NPTS)                       // 16384
#define NMAT   ((size_t)NBATCH * NPTS * NPTS)        // 33554432
#define MAX_IT 100

// eps = 0.1 ; 1/eps = 10 ; scale for base-2 exponentials: 10 * log2(e)
#define S2   14.4269504088896341f
#define LN2  0.6931471805599453f
#define EPSV 0.1f
// log(1/2048 + 1e-8) — constant-folded by the compiler (matches fp32 reference)
#define LOG_MUV (logf(1.0f / 2048.0f + 1e-8f))
#define LOG_NUV LOG_MUV
// err = mean over 8 batches of sum|du| ; mean < 0.1  <=>  sum < 0.8
#define ERR_THRESH_SUM 0.8f

// Scratch state (no device allocation allowed -> __device__ globals)
__device__ __align__(16) float g_u[NROWS];
__device__ __align__(16) float g_v[NROWS];
__device__ float g_err[MAX_IT];
__device__ int   g_done;

__device__ __forceinline__ float ex2f(float x) {
    float y;
    asm("ex2.approx.ftz.f32 %0, %1;" : "=f"(y) : "f"(x));
    return y;
}

// ---------------------------------------------------------------------------
// Init: zero u, v, err accumulators, done flag, and the 8 cost outputs.
// ---------------------------------------------------------------------------
__global__ void k_init(float* __restrict__ cost) {
    int t = blockIdx.x * blockDim.x + threadIdx.x;
    int n = gridDim.x * blockDim.x;
    for (int i = t; i < NROWS; i += n) {
        g_u[i] = 0.0f;
        g_v[i] = 0.0f;
    }
    if (t < MAX_IT) g_err[t] = 0.0f;
    if (t == 0) g_done = 0;
    if (t < NBATCH) cost[t] = 0.0f;
}

// ---------------------------------------------------------------------------
// Cost matrix: C[b,i,j] = sum_d (x[b,i,d] - y[b,j,d])^2
// One 64x64 tile per block, x/y tiles staged transposed in SMEM (padded 65).
// ---------------------------------------------------------------------------
__global__ void __launch_bounds__(256) k_cost(const float* __restrict__ x,
                                              const float* __restrict__ y,
                                              float* __restrict__ C) {
    __shared__ float xs[NFEAT * 65];
    __shared__ float ys[NFEAT * 65];

    int tile = blockIdx.x;          // 8 * 32 * 32 = 8192 tiles
    int b  = tile >> 10;
    int ti = (tile >> 5) & 31;
    int tj = tile & 31;
    int tid = threadIdx.x;

    const float* xb = x + ((size_t)b * NPTS + (size_t)ti * 64) * NFEAT;
    const float* yb = y + ((size_t)b * NPTS + (size_t)tj * 64) * NFEAT;

    for (int e = tid; e < 64 * NFEAT; e += 256) {
        int row = e >> 5;   // 0..63
        int d   = e & 31;
        xs[d * 65 + row] = xb[e];
        ys[d * 65 + row] = yb[e];
    }
    __syncthreads();

    int ri = (tid >> 4) << 2;   // 0..60
    int cj = (tid & 15) << 2;   // 0..60

    float acc[4][4];
#pragma unroll
    for (int a = 0; a < 4; a++)
#pragma unroll
        for (int c = 0; c < 4; c++) acc[a][c] = 0.0f;

#pragma unroll
    for (int d = 0; d < NFEAT; d++) {
        float xa[4], yv[4];
#pragma unroll
        for (int a = 0; a < 4; a++) xa[a] = xs[d * 65 + ri + a];
#pragma unroll
        for (int c = 0; c < 4; c++) yv[c] = ys[d * 65 + cj + c];
#pragma unroll
        for (int a = 0; a < 4; a++)
#pragma unroll
            for (int c = 0; c < 4; c++) {
                float diff = xa[a] - yv[c];
                acc[a][c] = fmaf(diff, diff, acc[a][c]);
            }
    }

    float* Cb = C + (size_t)b * NPTS * NPTS + (size_t)(ti * 64 + ri) * NPTS + (tj * 64 + cj);
#pragma unroll
    for (int a = 0; a < 4; a++) {
        float4 o = make_float4(acc[a][0], acc[a][1], acc[a][2], acc[a][3]);
        *reinterpret_cast<float4*>(Cb + (size_t)a * NPTS) = o;
    }
}

// ---------------------------------------------------------------------------
// u update: one warp per row r = (b, i).
// u_new = eps * (log_mu - lse_j((v_j - C_ij)/eps))
// Accumulate sum |u_new - u_old| into g_err[it] (block-staged atomics).
// ---------------------------------------------------------------------------
__global__ void __launch_bounds__(256) k_u(const float* __restrict__ C, int it) {
    if (g_done) return;
    __shared__ float blkerr;
    if (threadIdx.x == 0) blkerr = 0.0f;
    __syncthreads();

    int warp = (blockIdx.x << 3) + (threadIdx.x >> 5);   // row id, grid = 2048 blocks
    int lane = threadIdx.x & 31;
    int r = warp;
    int b = r >> 11;

    const float4* Cr = reinterpret_cast<const float4*>(C + (size_t)r * NPTS);
    const float4* Vr = reinterpret_cast<const float4*>(g_v + (b << 11));

    float m = -1e30f, s = 0.0f;
#pragma unroll 4
    for (int k = lane; k < NPTS / 4; k += 32) {
        float4 c = Cr[k];
        float4 v = Vr[k];
        float t0 = (v.x - c.x) * S2;
        float t1 = (v.y - c.y) * S2;
        float t2 = (v.z - c.z) * S2;
        float t3 = (v.w - c.w) * S2;
        float m4 = fmaxf(fmaxf(t0, t1), fmaxf(t2, t3));
        float nm = fmaxf(m, m4);
        s = s * ex2f(m - nm) + ((ex2f(t0 - nm) + ex2f(t1 - nm)) + (ex2f(t2 - nm) + ex2f(t3 - nm)));
        m = nm;
    }
#pragma unroll
    for (int o = 16; o; o >>= 1) {
        float mo = __shfl_xor_sync(0xffffffffu, m, o);
        float so = __shfl_xor_sync(0xffffffffu, s, o);
        float nm = fmaxf(m, mo);
        s = s * ex2f(m - nm) + so * ex2f(mo - nm);
        m = nm;
    }
    if (lane == 0) {
        float lse  = m * LN2 + logf(s);            // natural-log lse of (v - C)/eps
        float unew = EPSV * (LOG_MUV - lse);
        float du = fabsf(unew - g_u[r]);
        g_u[r] = unew;
        atomicAdd(&blkerr, du);
    }
    __syncthreads();
    if (threadIdx.x == 0) atomicAdd(&g_err[it], blkerr);
}

// ---------------------------------------------------------------------------
// v update: block handles 32 columns of one batch; 8 warps split the i-range.
// v_new = eps * (log_nu - lse_i((u_i - C_ij)/eps))
// ---------------------------------------------------------------------------
__global__ void __launch_bounds__(256) k_v(const float* __restrict__ C, int it) {
    if (g_done) return;
    __shared__ float shm[256];
    __shared__ float shs[256];

    int task = blockIdx.x;                 // 8 * 64 = 512 tasks
    int b  = task >> 6;
    int j  = ((task & 63) << 5) + (threadIdx.x & 31);
    int ig = threadIdx.x >> 5;             // i-segment 0..7 (256 rows each)

    const float* Cb = C + ((size_t)b << 22);
    const float* ub = g_u + (b << 11);

    float m = -1e30f, s = 0.0f;
    int i0 = ig << 8;
#pragma unroll 1
    for (int ii = 0; ii < 256; ii += 4) {
        int i = i0 + ii;
        float c0 = Cb[(size_t)(i + 0) * NPTS + j];
        float c1 = Cb[(size_t)(i + 1) * NPTS + j];
        float c2 = Cb[(size_t)(i + 2) * NPTS + j];
        float c3 = Cb[(size_t)(i + 3) * NPTS + j];
        float t0 = (ub[i + 0] - c0) * S2;
        float t1 = (ub[i + 1] - c1) * S2;
        float t2 = (ub[i + 2] - c2) * S2;
        float t3 = (ub[i + 3] - c3) * S2;
        float m4 = fmaxf(fmaxf(t0, t1), fmaxf(t2, t3));
        float nm = fmaxf(m, m4);
        s = s * ex2f(m - nm) + ((ex2f(t0 - nm) + ex2f(t1 - nm)) + (ex2f(t2 - nm) + ex2f(t3 - nm)));
        m = nm;
    }
    shm[threadIdx.x] = m;
    shs[threadIdx.x] = s;
    __syncthreads();
    if (threadIdx.x < 32) {
        float M = shm[threadIdx.x], S = shs[threadIdx.x];
#pragma unroll
        for (int g = 1; g < 8; g++) {
            float mo = shm[(g << 5) + threadIdx.x];
            float so = shs[(g << 5) + threadIdx.x];
            float nm = fmaxf(M, mo);
            S = S * ex2f(M - nm) + so * ex2f(mo - nm);
            M = nm;
        }
        float lse = M * LN2 + logf(S);
        g_v[(b << 11) + j] = EPSV * (LOG_NUV - lse);
    }
}

// ---------------------------------------------------------------------------
// Convergence check: runs after (U, V) of iteration `it`.
// Once sum|du| < 0.8, all subsequent U/V launches become no-ops (matches the
// reference's freeze semantics: the crossing iteration's V still applied).
// ---------------------------------------------------------------------------
__global__ void k_chk(int it) {
    if (g_err[it] < ERR_THRESH_SUM) g_done = 1;
}

// ---------------------------------------------------------------------------
// Epilogue: pi = exp((u_i + v_j - C_ij)/eps), cost[b] = sum_ij pi*C
// One warp per row; per-block cost staging (all 8 rows of a block share b).
// ---------------------------------------------------------------------------
__global__ void __launch_bounds__(256) k_pi(const float* __restrict__ C,
                                            float* __restrict__ pi,
                                            float* __restrict__ cost) {
    __shared__ float blkcost;
    if (threadIdx.x == 0) blkcost = 0.0f;
    __syncthreads();

    int warp = (blockIdx.x << 3) + (threadIdx.x >> 5);
    int lane = threadIdx.x & 31;
    int r = warp;
    int b = r >> 11;

    float u = g_u[r];
    const float4* Cr = reinterpret_cast<const float4*>(C + (size_t)r * NPTS);
    const float4* Vr = reinterpret_cast<const float4*>(g_v + (b << 11));
    float4* Pr = reinterpret_cast<float4*>(pi + (size_t)r * NPTS);

    float acc = 0.0f;
#pragma unroll 4
    for (int k = lane; k < NPTS / 4; k += 32) {
        float4 c = Cr[k];
        float4 v = Vr[k];
        float4 p;
        p.x = ex2f((u + v.x - c.x) * S2);
        p.y = ex2f((u + v.y - c.y) * S2);
        p.z = ex2f((u + v.z - c.z) * S2);
        p.w = ex2f((u + v.w - c.w) * S2);
        Pr[k] = p;
        acc += p.x * c.x + p.y * c.y + p.z * c.z + p.w * c.w;
    }
#pragma unroll
    for (int o = 16; o; o >>= 1) acc += __shfl_xor_sync(0xffffffffu, acc, o);
    if (lane == 0) atomicAdd(&blkcost, acc);
    __syncthreads();
    if (threadIdx.x == 0) atomicAdd(&cost[b], blkcost);
}

// ---------------------------------------------------------------------------
// Launch: init -> C -> 100 x (U, V, check) -> pi/cost.
// Output layout assumption (tuple order): cost[8] | pi[8*2048*2048] | C[...].
// All launches on the default stream; fully graph-capturable, no allocations.
// ---------------------------------------------------------------------------
extern "C" void kernel_launch(void* const* d_in, const int* in_sizes, int n_in,
                              void* d_out, int out_size) {
    const float* x = (const float*)d_in[0];
    const float* y = (const float*)d_in[1];
    float* out  = (float*)d_out;
    float* cost = out;
    float* pi   = out + NBATCH;
    float* C    = out + NBATCH + NMAT;

    k_init<<<64, 256>>>(cost);
    k_cost<<<NBATCH * 32 * 32, 256>>>(x, y, C);
    for (int it = 0; it < MAX_IT; it++) {
        k_u<<<NROWS / 8, 256>>>(C, it);
        k_v<<<512, 256>>>(C, it);
        k_chk<<<1, 1>>>(it);
    }
    k_pi<<<NROWS / 8, 256>>>(C, pi, cost);
}

// round 2
// speedup vs baseline: 1.0083x; 1.0083x over previous
#include <cuda_runtime.h>
#include <math.h>

// Problem constants
#define NBATCH 8
#define NPTS   2048
#define NFEAT  32
#define NROWS  (NBATCH * NPTS)                       // 16384
#define NMAT   ((size_t)NBATCH * NPTS * NPTS)        // 33554432
#define MAX_IT 100
#define RB     64                                    // rows per block slice
#define RBLK   (NPTS / RB)                           // 32 row-blocks per batch

// eps = 0.1 ; scale for base-2 exponentials: (1/eps) * log2(e)
#define S2   14.4269504088896341f
#define LN2  0.6931471805599453f
#define EPSV 0.1f
#define LOG_MUV (logf(1.0f / 2048.0f + 1e-8f))
#define LOG_NUV LOG_MUV
// err = mean over 8 batches of sum|du| < 0.1  <=>  total sum < 0.8
#define ERR_THRESH_SUM 0.8f

// Scratch state (no device allocation allowed -> __device__ globals)
__device__ __align__(16) float g_u[NROWS];
__device__ __align__(16) float g_v[NROWS];
__device__ float g_err[MAX_IT];
__device__ __align__(16) float g_pm[NBATCH * RBLK * NPTS];   // column lse partial max
__device__ __align__(16) float g_ps[NBATCH * RBLK * NPTS];   // column lse partial sum

__device__ __forceinline__ float ex2f(float x) {
    float y;
    asm("ex2.approx.ftz.f32 %0, %1;" : "=f"(y) : "f"(x));
    return y;
}

// ---------------------------------------------------------------------------
// Init: zero u, v, err accumulators, and the 8 cost outputs.
// ---------------------------------------------------------------------------
__global__ void k_init(float* __restrict__ cost) {
    int t = blockIdx.x * blockDim.x + threadIdx.x;
    int n = gridDim.x * blockDim.x;
    for (int i = t; i < NROWS; i += n) {
        g_u[i] = 0.0f;
        g_v[i] = 0.0f;
    }
    if (t < MAX_IT) g_err[t] = 0.0f;
    if (t < NBATCH) cost[t] = 0.0f;
}

// ---------------------------------------------------------------------------
// Cost matrix: C[b,i,j] = sum_d (x[b,i,d] - y[b,j,d])^2
// One 64x64 tile per block, x/y tiles staged transposed in SMEM (padded 65).
// ---------------------------------------------------------------------------
__global__ void __launch_bounds__(256) k_cost(const float* __restrict__ x,
                                              const float* __restrict__ y,
                                              float* __restrict__ C) {
    __shared__ float xs[NFEAT * 65];
    __shared__ float ys[NFEAT * 65];

    int tile = blockIdx.x;          // 8 * 32 * 32 = 8192 tiles
    int b  = tile >> 10;
    int ti = (tile >> 5) & 31;
    int tj = tile & 31;
    int tid = threadIdx.x;

    const float* xb = x + ((size_t)b * NPTS + (size_t)ti * 64) * NFEAT;
    const float* yb = y + ((size_t)b * NPTS + (size_t)tj * 64) * NFEAT;

    for (int e = tid; e < 64 * NFEAT; e += 256) {
        int row = e >> 5;
        int d   = e & 31;
        xs[d * 65 + row] = xb[e];
        ys[d * 65 + row] = yb[e];
    }
    __syncthreads();

    int ri = (tid >> 4) << 2;
    int cj = (tid & 15) << 2;

    float acc[4][4];
#pragma unroll
    for (int a = 0; a < 4; a++)
#pragma unroll
        for (int c = 0; c < 4; c++) acc[a][c] = 0.0f;

#pragma unroll
    for (int d = 0; d < NFEAT; d++) {
        float xa[4], yv[4];
#pragma unroll
        for (int a = 0; a < 4; a++) xa[a] = xs[d * 65 + ri + a];
#pragma unroll
        for (int c = 0; c < 4; c++) yv[c] = ys[d * 65 + cj + c];
#pragma unroll
        for (int a = 0; a < 4; a++)
#pragma unroll
            for (int c = 0; c < 4; c++) {
                float diff = xa[a] - yv[c];
                acc[a][c] = fmaf(diff, diff, acc[a][c]);
            }
    }

    float* Cb = C + (size_t)b * NPTS * NPTS + (size_t)(ti * 64 + ri) * NPTS + (tj * 64 + cj);
#pragma unroll
    for (int a = 0; a < 4; a++) {
        float4 o = make_float4(acc[a][0], acc[a][1], acc[a][2], acc[a][3]);
        *reinterpret_cast<float4*>(Cb + (size_t)a * NPTS) = o;
    }
}

// ---------------------------------------------------------------------------
// Fused Sinkhorn iteration: single pass over C.
// Block = (batch b, row-block rb of 64 rows). Per 8-row chunk:
//   phase 1: warp w computes u_new for row chunk*8+w (row-wise online LSE)
//   phase 2: all warps fold those 8 rows (hot in L2) into per-column online
//            LSE accumulators (warp w owns columns [w*256, w*256+256)).
// Partial (m,s) per column written to scratch; k_vred merges 32 partials -> v.
// Early freeze: g_err[it-1] < thresh (sticky: frozen iters leave g_err = 0).
// ---------------------------------------------------------------------------
__global__ void __launch_bounds__(256) k_iter(const float* __restrict__ C, int it) {
    if (it > 0 && g_err[it - 1] < ERR_THRESH_SUM) return;

    __shared__ float v_s[NPTS];
    __shared__ float u_s[RB];
    __shared__ float blkerr;

    int blk = blockIdx.x;          // 8 * 32 = 256 blocks
    int b   = blk >> 5;
    int rb  = blk & 31;
    int tid = threadIdx.x;
    int w   = tid >> 5;
    int l   = tid & 31;

    const float4* vg  = reinterpret_cast<const float4*>(g_v + (b << 11));
    float4*       vs4 = reinterpret_cast<float4*>(v_s);
#pragma unroll
    for (int k = 0; k < 2; k++) vs4[tid + 256 * k] = vg[tid + 256 * k];
    if (tid == 0) blkerr = 0.0f;
    __syncthreads();

    const float* Cb = C + ((size_t)b << 22) + (((size_t)rb * RB) << 11);
    int cq = (w << 6) + l;   // float4 column index: warp base w*256/4 + lane

    // column accumulators: slots 0..3 -> cols 4*cq..4*cq+3 ; 4..7 -> +128
    float cm[8], cs[8];
#pragma unroll
    for (int q = 0; q < 8; q++) { cm[q] = -1e30f; cs[q] = 0.0f; }

    for (int ch = 0; ch < RB / 8; ch++) {
        // ---- phase 1: u for row rl = ch*8 + w ----
        int rl = (ch << 3) + w;
        const float4* Cr = reinterpret_cast<const float4*>(Cb + ((size_t)rl << 11));
        float rm = -1e30f, rs = 0.0f;
#pragma unroll
        for (int g = 0; g < 8; g++) {
            float4 c0 = Cr[l + (g << 6)];
            float4 c1 = Cr[l + 32 + (g << 6)];
            float4 v0 = vs4[l + (g << 6)];
            float4 v1 = vs4[l + 32 + (g << 6)];
            float t0 = (v0.x - c0.x) * S2;
            float t1 = (v0.y - c0.y) * S2;
            float t2 = (v0.z - c0.z) * S2;
            float t3 = (v0.w - c0.w) * S2;
            float t4 = (v1.x - c1.x) * S2;
            float t5 = (v1.y - c1.y) * S2;
            float t6 = (v1.z - c1.z) * S2;
            float t7 = (v1.w - c1.w) * S2;
            float m8 = fmaxf(fmaxf(fmaxf(t0, t1), fmaxf(t2, t3)),
                             fmaxf(fmaxf(t4, t5), fmaxf(t6, t7)));
            float nm = fmaxf(rm, m8);
            rs = rs * ex2f(rm - nm)
               + (((ex2f(t0 - nm) + ex2f(t1 - nm)) + (ex2f(t2 - nm) + ex2f(t3 - nm)))
                + ((ex2f(t4 - nm) + ex2f(t5 - nm)) + (ex2f(t6 - nm) + ex2f(t7 - nm))));
            rm = nm;
        }
#pragma unroll
        for (int o = 16; o; o >>= 1) {
            float mo = __shfl_xor_sync(0xffffffffu, rm, o);
            float so = __shfl_xor_sync(0xffffffffu, rs, o);
            float nm = fmaxf(rm, mo);
            rs = rs * ex2f(rm - nm) + so * ex2f(mo - nm);
            rm = nm;
        }
        float unew = EPSV * (LOG_MUV - (rm * LN2 + logf(rs)));
        if (l == 0) {
            int row = (b << 11) + rb * RB + rl;
            float du = fabsf(unew - g_u[row]);
            g_u[row] = unew;
            u_s[rl]  = unew;
            atomicAdd(&blkerr, du);
        }
        __syncthreads();   // u_s[ch*8 .. ch*8+7] ready for all warps

        // ---- phase 2: fold 8 hot rows into column accumulators ----
#pragma unroll
        for (int half = 0; half < 2; half++) {
            int i0 = (ch << 3) + (half << 2);
            float4 ca[4], cb2[4];
            float  uu[4];
#pragma unroll
            for (int r = 0; r < 4; r++) {
                const float4* Ri = reinterpret_cast<const float4*>(Cb + ((size_t)(i0 + r) << 11));
                ca[r]  = Ri[cq];
                cb2[r] = Ri[cq + 32];
                uu[r]  = u_s[i0 + r];
            }
#define COLUPD(q, e0, e1, e2, e3)                                              \
            {                                                                  \
                float t0 = (uu[0] - (e0)) * S2;                                \
                float t1 = (uu[1] - (e1)) * S2;                                \
                float t2 = (uu[2] - (e2)) * S2;                                \
                float t3 = (uu[3] - (e3)) * S2;                                \
                float m4 = fmaxf(fmaxf(t0, t1), fmaxf(t2, t3));                \
                float nm = fmaxf(cm[q], m4);                                   \
                cs[q] = cs[q] * ex2f(cm[q] - nm)                               \
                      + ((ex2f(t0 - nm) + ex2f(t1 - nm))                       \
                       + (ex2f(t2 - nm) + ex2f(t3 - nm)));                     \
                cm[q] = nm;                                                    \
            }
            COLUPD(0, ca[0].x,  ca[1].x,  ca[2].x,  ca[3].x)
            COLUPD(1, ca[0].y,  ca[1].y,  ca[2].y,  ca[3].y)
            COLUPD(2, ca[0].z,  ca[1].z,  ca[2].z,  ca[3].z)
            COLUPD(3, ca[0].w,  ca[1].w,  ca[2].w,  ca[3].w)
            COLUPD(4, cb2[0].x, cb2[1].x, cb2[2].x, cb2[3].x)
            COLUPD(5, cb2[0].y, cb2[1].y, cb2[2].y, cb2[3].y)
            COLUPD(6, cb2[0].z, cb2[1].z, cb2[2].z, cb2[3].z)
            COLUPD(7, cb2[0].w, cb2[1].w, cb2[2].w, cb2[3].w)
#undef COLUPD
        }
    }

    __syncthreads();
    if (tid == 0) atomicAdd(&g_err[it], blkerr);

    // write column partials (coalesced float4)
    size_t pb = ((size_t)(b * RBLK + rb)) << 11;
    float4* pm4 = reinterpret_cast<float4*>(g_pm + pb);
    float4* ps4 = reinterpret_cast<float4*>(g_ps + pb);
    pm4[cq]      = make_float4(cm[0], cm[1], cm[2], cm[3]);
    ps4[cq]      = make_float4(cs[0], cs[1], cs[2], cs[3]);
    pm4[cq + 32] = make_float4(cm[4], cm[5], cm[6], cm[7]);
    ps4[cq + 32] = make_float4(cs[4], cs[5], cs[6], cs[7]);
}

// ---------------------------------------------------------------------------
// Merge 32 per-column partials -> v_new. One thread per (batch, column).
// ---------------------------------------------------------------------------
__global__ void __launch_bounds__(256) k_vred(int it) {
    if (it > 0 && g_err[it - 1] < ERR_THRESH_SUM) return;
    int t   = blockIdx.x * 256 + threadIdx.x;   // 16384 threads
    int b   = t >> 11;
    int col = t & 2047;
    size_t base = (((size_t)b * RBLK) << 11) + col;
    float m = -1e30f, s = 0.0f;
#pragma unroll
    for (int p = 0; p < RBLK; p++) {
        float mo = g_pm[base + ((size_t)p << 11)];
        float so = g_ps[base + ((size_t)p << 11)];
        float nm = fmaxf(m, mo);
        s = s * ex2f(m - nm) + so * ex2f(mo - nm);
        m = nm;
    }
    g_v[(b << 11) + col] = EPSV * (LOG_NUV - (m * LN2 + logf(s)));
}

// ---------------------------------------------------------------------------
// Epilogue: pi = exp((u_i + v_j - C_ij)/eps), cost[b] = sum_ij pi*C
// ---------------------------------------------------------------------------
__global__ void __launch_bounds__(256) k_pi(const float* __restrict__ C,
                                            float* __restrict__ pi,
                                            float* __restrict__ cost) {
    __shared__ float blkcost;
    if (threadIdx.x == 0) blkcost = 0.0f;
    __syncthreads();

    int warp = (blockIdx.x << 3) + (threadIdx.x >> 5);
    int lane = threadIdx.x & 31;
    int r = warp;
    int b = r >> 11;

    float u = g_u[r];
    const float4* Cr = reinterpret_cast<const float4*>(C + (size_t)r * NPTS);
    const float4* Vr = reinterpret_cast<const float4*>(g_v + (b << 11));
    float4* Pr = reinterpret_cast<float4*>(pi + (size_t)r * NPTS);

    float acc = 0.0f;
#pragma unroll 4
    for (int k = lane; k < NPTS / 4; k += 32) {
        float4 c = Cr[k];
        float4 v = Vr[k];
        float4 p;
        p.x = ex2f((u + v.x - c.x) * S2);
        p.y = ex2f((u + v.y - c.y) * S2);
        p.z = ex2f((u + v.z - c.z) * S2);
        p.w = ex2f((u + v.w - c.w) * S2);
        Pr[k] = p;
        acc += p.x * c.x + p.y * c.y + p.z * c.z + p.w * c.w;
    }
#pragma unroll
    for (int o = 16; o; o >>= 1) acc += __shfl_xor_sync(0xffffffffu, acc, o);
    if (lane == 0) atomicAdd(&blkcost, acc);
    __syncthreads();
    if (threadIdx.x == 0) atomicAdd(&cost[b], blkcost);
}

// ---------------------------------------------------------------------------
// Launch: init -> C -> 100 x (fused iter, v-reduce) -> pi/cost.
// Output layout (tuple order): cost[8] | pi[8*2048*2048] | C[8*2048*2048].
// ---------------------------------------------------------------------------
extern "C" void kernel_launch(void* const* d_in, const int* in_sizes, int n_in,
                              void* d_out, int out_size) {
    const float* x = (const float*)d_in[0];
    const float* y = (const float*)d_in[1];
    float* out  = (float*)d_out;
    float* cost = out;
    float* pi   = out + NBATCH;
    float* C    = out + NBATCH + NMAT;

    k_init<<<64, 256>>>(cost);
    k_cost<<<NBATCH * 32 * 32, 256>>>(x, y, C);
    for (int it = 0; it < MAX_IT; it++) {
        k_iter<<<NBATCH * RBLK, 256>>>(C, it);
        k_vred<<<64, 256>>>(it);
    }
    k_pi<<<NROWS / 8, 256>>>(C, pi, cost);
}

// round 4
// speedup vs baseline: 1.2210x; 1.2110x over previous
#include <cuda_runtime.h>
#include <math.h>

// Problem constants
#define NBATCH 8
#define NPTS   2048
#define NFEAT  32
#define NROWS  (NBATCH * NPTS)                       // 16384
#define NMAT   ((size_t)NBATCH * NPTS * NPTS)        // 33554432
#define MAX_IT 100
#define RB     16                                    // rows per iter block
#define RBLK   (NPTS / RB)                           // 128 row-blocks per batch

// eps = 0.1 ; log2-domain scale: (1/eps) * log2(e)
#define S2   14.4269504088896341f
#define LN2  0.6931471805599453f
#define EPSV 0.1f
#define LOG_MUV (logf(1.0f / 2048.0f + 1e-8f))
#define LOG_NUV LOG_MUV
#define ERR_THRESH_SUM 0.8f

// Scratch (__device__ globals; no allocation allowed)
__device__ __align__(16) float g_u[NROWS];
__device__ __align__(16) float g_v[NROWS];
__device__ float g_err[MAX_IT];
__device__ __align__(16) float g_pm[NBATCH * RBLK * NPTS];   // 8 MB col partial max
__device__ __align__(16) float g_ps[NBATCH * RBLK * NPTS];   // 8 MB col partial sum
__device__ __align__(16) float g_pm2[NBATCH * 8 * NPTS];     // stage-2 partials
__device__ __align__(16) float g_ps2[NBATCH * 8 * NPTS];

__device__ __forceinline__ float ex2f(float x) {
    float y;
    asm("ex2.approx.ftz.f32 %0, %1;" : "=f"(y) : "f"(x));
    return y;
}

// ---------------------------------------------------------------------------
// Init
// ---------------------------------------------------------------------------
__global__ void k_init(float* __restrict__ cost) {
    int t = blockIdx.x * blockDim.x + threadIdx.x;
    int n = gridDim.x * blockDim.x;
    for (int i = t; i < NROWS; i += n) {
        g_u[i] = 0.0f;
        g_v[i] = 0.0f;
    }
    if (t < MAX_IT) g_err[t] = 0.0f;
    if (t < NBATCH) cost[t] = 0.0f;
}

// ---------------------------------------------------------------------------
// Cost matrix: C[b,i,j] = sum_d (x[b,i,d] - y[b,j,d])^2
// ---------------------------------------------------------------------------
__global__ void __launch_bounds__(256) k_cost(const float* __restrict__ x,
                                              const float* __restrict__ y,
                                              float* __restrict__ C) {
    __shared__ float xs[NFEAT * 65];
    __shared__ float ys[NFEAT * 65];

    int tile = blockIdx.x;          // 8192 tiles of 64x64
    int b  = tile >> 10;
    int ti = (tile >> 5) & 31;
    int tj = tile & 31;
    int tid = threadIdx.x;

    const float* xb = x + ((size_t)b * NPTS + (size_t)ti * 64) * NFEAT;
    const float* yb = y + ((size_t)b * NPTS + (size_t)tj * 64) * NFEAT;

    for (int e = tid; e < 64 * NFEAT; e += 256) {
        int row = e >> 5;
        int d   = e & 31;
        xs[d * 65 + row] = xb[e];
        ys[d * 65 + row] = yb[e];
    }
    __syncthreads();

    int ri = (tid >> 4) << 2;
    int cj = (tid & 15) << 2;

    float acc[4][4];
#pragma unroll
    for (int a = 0; a < 4; a++)
#pragma unroll
        for (int c = 0; c < 4; c++) acc[a][c] = 0.0f;

#pragma unroll
    for (int d = 0; d < NFEAT; d++) {
        float xa[4], yv[4];
#pragma unroll
        for (int a = 0; a < 4; a++) xa[a] = xs[d * 65 + ri + a];
#pragma unroll
        for (int c = 0; c < 4; c++) yv[c] = ys[d * 65 + cj + c];
#pragma unroll
        for (int a = 0; a < 4; a++)
#pragma unroll
            for (int c = 0; c < 4; c++) {
                float diff = xa[a] - yv[c];
                acc[a][c] = fmaf(diff, diff, acc[a][c]);
            }
    }

    float* Cb = C + (size_t)b * NPTS * NPTS + (size_t)(ti * 64 + ri) * NPTS + (tj * 64 + cj);
#pragma unroll
    for (int a = 0; a < 4; a++) {
        float4 o = make_float4(acc[a][0], acc[a][1], acc[a][2], acc[a][3]);
        *reinterpret_cast<float4*>(Cb + (size_t)a * NPTS) = o;
    }
}

// ---------------------------------------------------------------------------
// Fused iteration, exact LSE both sides, single pass over C.
// Block = 128 threads (4 warps), 16 rows, 4 chunks of 4 rows.
// Phase 1 (per chunk): warp w scans row w: t = (v - C)*S2 -> smem, grouped
//   online LSE (8-wide) -> u_new, uS2 to smem.
// Phase 2: per-column grouped (4-row) online LSE fold of the smem t-tile
//   into register accumulators (cm, cs). Exact column max -> no under/overflow.
// Partials written per block; merged by k_vredA/k_vredB.
// Early freeze: g_err[it-1] < thresh (sticky: frozen iters leave g_err = 0).
// ---------------------------------------------------------------------------
__global__ void __launch_bounds__(128) k_iter(const float* __restrict__ C, int it) {
    if (it > 0 && g_err[it - 1] < ERR_THRESH_SUM) return;

    __shared__ float vS2_s[NPTS];        // 8 KB : v * S2
    __shared__ float t_s[4 * NPTS];      // 32 KB : t tile, 4 rows
    __shared__ float uS2_s[4];
    __shared__ float blkerr;

    int blk = blockIdx.x;                // 8 * 128 = 1024 blocks
    int b   = blk >> 7;
    int rb  = blk & 127;
    int tid = threadIdx.x;
    int w   = tid >> 5;
    int l   = tid & 31;

    const float4* vg  = reinterpret_cast<const float4*>(g_v + (b << 11));
    float4*       vs4 = reinterpret_cast<float4*>(vS2_s);
#pragma unroll
    for (int k = 0; k < 4; k++) {
        float4 t = vg[tid + (k << 7)];
        t.x *= S2; t.y *= S2; t.z *= S2; t.w *= S2;
        vs4[tid + (k << 7)] = t;
    }
    if (tid == 0) blkerr = 0.0f;
    __syncthreads();

    const float* Cb = C + ((size_t)b << 22) + (((size_t)rb * RB) << 11);
    int cq = (w << 7) + l;               // float4 col index; warp owns 512 cols

    float cm[16], cs[16];
#pragma unroll
    for (int q = 0; q < 16; q++) { cm[q] = -1e30f; cs[q] = 0.0f; }

    float4* ts_all = reinterpret_cast<float4*>(t_s);

#pragma unroll 1
    for (int ch = 0; ch < RB / 4; ch++) {
        // ---- phase 1: row rl = ch*4 + w ----
        int rl = (ch << 2) + w;
        int r  = (b << 11) + rb * RB + rl;
        const float4* Cr  = reinterpret_cast<const float4*>(Cb + ((size_t)rl << 11));
        float4*       ts4 = ts_all + (w << 9);     // warp's 512-float4 row slot

        float m = -1e30f, s = 0.0f;
#pragma unroll
        for (int g = 0; g < 8; g++) {
            int idx = l + (g << 6);
            float4 c0 = Cr[idx];
            float4 c1 = Cr[idx + 32];
            float4 v0 = vs4[idx];
            float4 v1 = vs4[idx + 32];
            float t0 = fmaf(-S2, c0.x, v0.x);
            float t1 = fmaf(-S2, c0.y, v0.y);
            float t2 = fmaf(-S2, c0.z, v0.z);
            float t3 = fmaf(-S2, c0.w, v0.w);
            float t4 = fmaf(-S2, c1.x, v1.x);
            float t5 = fmaf(-S2, c1.y, v1.y);
            float t6 = fmaf(-S2, c1.z, v1.z);
            float t7 = fmaf(-S2, c1.w, v1.w);
            ts4[idx]      = make_float4(t0, t1, t2, t3);
            ts4[idx + 32] = make_float4(t4, t5, t6, t7);
            float m8 = fmaxf(fmaxf(fmaxf(t0, t1), fmaxf(t2, t3)),
                             fmaxf(fmaxf(t4, t5), fmaxf(t6, t7)));
            float nm = fmaxf(m, m8);
            s = s * ex2f(m - nm)
              + (((ex2f(t0 - nm) + ex2f(t1 - nm)) + (ex2f(t2 - nm) + ex2f(t3 - nm)))
               + ((ex2f(t4 - nm) + ex2f(t5 - nm)) + (ex2f(t6 - nm) + ex2f(t7 - nm))));
            m = nm;
        }
#pragma unroll
        for (int o = 16; o; o >>= 1) {
            float mo = __shfl_xor_sync(0xffffffffu, m, o);
            float so = __shfl_xor_sync(0xffffffffu, s, o);
            float nm = fmaxf(m, mo);
            s = s * ex2f(m - nm) + so * ex2f(mo - nm);
            m = nm;
        }
        if (l == 0) {
            float lse  = m * LN2 + logf(s);        // natural-log lse of (v - C)/eps
            float unew = EPSV * (LOG_MUV - lse);
            float du = fabsf(unew - g_u[r]);
            g_u[r]   = unew;
            uS2_s[w] = unew * S2;
            atomicAdd(&blkerr, du);
        }
        __syncthreads();   // t tile + uS2 ready

        // ---- phase 2: grouped 4-row online column LSE ----
        float us0 = uS2_s[0], us1 = uS2_s[1], us2 = uS2_s[2], us3 = uS2_s[3];
#pragma unroll
        for (int g = 0; g < 4; g++) {
            int idx = cq + (g << 5);
            float4 t0 = ts_all[idx];
            float4 t1 = ts_all[512 + idx];
            float4 t2 = ts_all[1024 + idx];
            float4 t3 = ts_all[1536 + idx];
#define COLUPD(q, e0, e1, e2, e3)                                              \
            {                                                                  \
                float a0 = (e0) + us0;                                         \
                float a1 = (e1) + us1;                                         \
                float a2 = (e2) + us2;                                         \
                float a3 = (e3) + us3;                                         \
                float m4 = fmaxf(fmaxf(a0, a1), fmaxf(a2, a3));                \
                float nm = fmaxf(cm[q], m4);                                   \
                cs[q] = cs[q] * ex2f(cm[q] - nm)                               \
                      + ((ex2f(a0 - nm) + ex2f(a1 - nm))                       \
                       + (ex2f(a2 - nm) + ex2f(a3 - nm)));                     \
                cm[q] = nm;                                                    \
            }
            COLUPD(4 * g + 0, t0.x, t1.x, t2.x, t3.x)
            COLUPD(4 * g + 1, t0.y, t1.y, t2.y, t3.y)
            COLUPD(4 * g + 2, t0.z, t1.z, t2.z, t3.z)
            COLUPD(4 * g + 3, t0.w, t1.w, t2.w, t3.w)
#undef COLUPD
        }
        __syncthreads();   // protect t tile before next chunk rewrites it
    }

    // write column partials (coalesced float4)
    size_t pb = ((size_t)blk) << 11;
    float4* pm4 = reinterpret_cast<float4*>(g_pm + pb);
    float4* ps4 = reinterpret_cast<float4*>(g_ps + pb);
#pragma unroll
    for (int g = 0; g < 4; g++) {
        pm4[cq + (g << 5)] = make_float4(cm[4*g], cm[4*g+1], cm[4*g+2], cm[4*g+3]);
        ps4[cq + (g << 5)] = make_float4(cs[4*g], cs[4*g+1], cs[4*g+2], cs[4*g+3]);
    }
    if (tid == 0) atomicAdd(&g_err[it], blkerr);
}

// ---------------------------------------------------------------------------
// v reduce, stage A: merge 16 partials -> 8 per column. 128K threads.
// ---------------------------------------------------------------------------
__global__ void __launch_bounds__(256) k_vredA(int it) {
    if (it > 0 && g_err[it - 1] < ERR_THRESH_SUM) return;
    int t   = blockIdx.x * 256 + threadIdx.x;    // 512 blocks -> 131072 threads
    int col = t & 2047;
    int pg  = (t >> 11) & 7;
    int b   = t >> 14;
    size_t base = (((size_t)(b * RBLK + pg * 16)) << 11) + col;
    float m = -1e30f, s = 0.0f;
#pragma unroll
    for (int k = 0; k < 16; k++) {
        float mo = g_pm[base + ((size_t)k << 11)];
        float so = g_ps[base + ((size_t)k << 11)];
        float nm = fmaxf(m, mo);
        s = s * ex2f(m - nm) + so * ex2f(mo - nm);
        m = nm;
    }
    size_t o = (((size_t)(b * 8 + pg)) << 11) + col;
    g_pm2[o] = m;
    g_ps2[o] = s;
}

// ---------------------------------------------------------------------------
// v reduce, stage B: merge 8 -> v_new = v + eps*(log_nu - lse).
// ---------------------------------------------------------------------------
__global__ void __launch_bounds__(256) k_vredB(int it) {
    if (it > 0 && g_err[it - 1] < ERR_THRESH_SUM) return;
    int t   = blockIdx.x * 256 + threadIdx.x;    // 64 blocks -> 16384 threads
    int col = t & 2047;
    int b   = t >> 11;
    size_t base = (((size_t)(b * 8)) << 11) + col;
    float m = -1e30f, s = 0.0f;
#pragma unroll
    for (int k = 0; k < 8; k++) {
        float mo = g_pm2[base + ((size_t)k << 11)];
        float so = g_ps2[base + ((size_t)k << 11)];
        float nm = fmaxf(m, mo);
        s = s * ex2f(m - nm) + so * ex2f(mo - nm);
        m = nm;
    }
    int j = (b << 11) + col;
    // a-domain included v, so: v_new = v_old + eps*(log_nu - lse)
    g_v[j] = g_v[j] + EPSV * (LOG_NUV - (m * LN2 + logf(s)));
}

// ---------------------------------------------------------------------------
// Epilogue: pi = exp((u_i + v_j - C_ij)/eps), cost[b] = sum pi*C
// ---------------------------------------------------------------------------
__global__ void __launch_bounds__(256) k_pi(const float* __restrict__ C,
                                            float* __restrict__ pi,
                                            float* __restrict__ cost) {
    __shared__ float blkcost;
    if (threadIdx.x == 0) blkcost = 0.0f;
    __syncthreads();

    int warp = (blockIdx.x << 3) + (threadIdx.x >> 5);
    int lane = threadIdx.x & 31;
    int r = warp;
    int b = r >> 11;

    float u = g_u[r];
    const float4* Cr = reinterpret_cast<const float4*>(C + (size_t)r * NPTS);
    const float4* Vr = reinterpret_cast<const float4*>(g_v + (b << 11));
    float4* Pr = reinterpret_cast<float4*>(pi + (size_t)r * NPTS);

    float acc = 0.0f;
#pragma unroll 4
    for (int k = lane; k < NPTS / 4; k += 32) {
        float4 c = Cr[k];
        float4 v = Vr[k];
        float4 p;
        p.x = ex2f((u + v.x - c.x) * S2);
        p.y = ex2f((u + v.y - c.y) * S2);
        p.z = ex2f((u + v.z - c.z) * S2);
        p.w = ex2f((u + v.w - c.w) * S2);
        Pr[k] = p;
        acc += p.x * c.x + p.y * c.y + p.z * c.z + p.w * c.w;
    }
#pragma unroll
    for (int o = 16; o; o >>= 1) acc += __shfl_xor_sync(0xffffffffu, acc, o);
    if (lane == 0) atomicAdd(&blkcost, acc);
    __syncthreads();
    if (threadIdx.x == 0) atomicAdd(&cost[b], blkcost);
}

// ---------------------------------------------------------------------------
// Launch
// ---------------------------------------------------------------------------
extern "C" void kernel_launch(void* const* d_in, const int* in_sizes, int n_in,
                              void* d_out, int out_size) {
    const float* x = (const float*)d_in[0];
    const float* y = (const float*)d_in[1];
    float* out  = (float*)d_out;
    float* cost = out;
    float* pi   = out + NBATCH;
    float* C    = out + NBATCH + NMAT;

    k_init<<<64, 256>>>(cost);
    k_cost<<<NBATCH * 32 * 32, 256>>>(x, y, C);
    for (int it = 0; it < MAX_IT; it++) {
        k_iter<<<NBATCH * RBLK, 128>>>(C, it);
        k_vredA<<<512, 256>>>(it);
        k_vredB<<<64, 256>>>(it);
    }
    k_pi<<<NROWS / 8, 256>>>(C, pi, cost);
}